// round 7
// baseline (speedup 1.0000x reference)
#include <cuda_runtime.h>
#include <math.h>

#define NB 32
#define NA 32768
#define NG 64
#define NC 91
#define RT 0.3103448275862069f   /* 0.45/1.45 : iou>=0.45  <=>  r=inter/S >= RT */
#define CLIPV 4.135166556742356f /* log(1000/16) */

// ---------------- scratch (static device globals; no runtime allocation) ----------------
__device__ int                 g_matched[NB * NA];
__device__ unsigned long long  g_best_gt[NB * NG];
__device__ unsigned            g_negkey[NB * NA];
__device__ int                 g_fgcnt[NB];
__device__ double              g_bbox_sum;
__device__ double              g_fgcls_sum;
__device__ double              g_neg_sum;

// ---------------- K0: zero accumulators (runs every replay) ----------------
__global__ void k_init() {
    int t = threadIdx.x;
    for (int i = t; i < NB * NG; i += blockDim.x) g_best_gt[i] = 0ull;
    if (t < NB) g_fgcnt[t] = 0;
    if (t == 0) { g_bbox_sum = 0.0; g_fgcls_sum = 0.0; g_neg_sum = 0.0; }
}

// ---------------- K1: IoU matching, 4 anchors/thread (high occupancy) ----------------
// grid (NA/1024, NB), block 256. r = inter/(area_g+area_a): monotone in IoU.
__global__ void __launch_bounds__(256) k_match(const float4* __restrict__ anchors,
                                               const float4* __restrict__ gt) {
    __shared__ float4 sgt[NG];
    __shared__ float  sga[NG];
    __shared__ unsigned long long sbest[NG];
    const int b = blockIdx.y;
    const int t = threadIdx.x;
    const int lane = t & 31;
    if (t < NG) {
        float4 g = gt[b * NG + t];
        sgt[t] = g;
        sga[t] = (g.z - g.x) * (g.w - g.y);
        sbest[t] = 0ull;
    }
    __syncthreads();

    const int a0 = blockIdx.x * 1024 + t;  // anchors a0 + j*256, j=0..3
    float ax0[4], ay0[4], ax1[4], ay1[4], aar[4], bv[4];
    int bg[4];
#pragma unroll
    for (int j = 0; j < 4; j++) {
        float4 a = anchors[(size_t)b * NA + a0 + j * 256];
        ax0[j] = a.x; ay0[j] = a.y; ax1[j] = a.z; ay1[j] = a.w;
        aar[j] = (a.z - a.x) * (a.w - a.y);
        bv[j] = 0.0f; bg[j] = 0;
    }

#pragma unroll
    for (int c = 0; c < 2; c++) {
        const int base = c * 32;
        unsigned long long acc = 0ull;  // per-gt best for g = base + lane
        for (int i = 0; i < 32; i++) {
            const int g = base + ((lane + i) & 31);
            const float4 gb = sgt[g];
            const float  ga = sga[g];
            float cr = 0.0f; int ca = a0;
#pragma unroll
            for (int j = 0; j < 4; j++) {
                float w = fminf(gb.z, ax1[j]) - fmaxf(gb.x, ax0[j]);
                float h = fminf(gb.w, ay1[j]) - fmaxf(gb.y, ay0[j]);
                w = fmaxf(w, 0.0f); h = fmaxf(h, 0.0f);
                float inter = w * h;
                float r = __fdividef(inter, ga + aar[j]);
                if (r > bv[j]) { bv[j] = r; bg[j] = g; }        // first g wins ties
                if (r > cr)    { cr = r; ca = a0 + j * 256; }   // lowest anchor wins ties
            }
            unsigned long long cand =
                ((unsigned long long)__float_as_uint(cr) << 32) |
                (unsigned long long)(0xFFFFFFFFu - (unsigned)ca);
            unsigned long long recv = __shfl_sync(0xFFFFFFFFu, cand, (lane - i) & 31);
            acc = (recv > acc) ? recv : acc;
        }
        atomicMax(&sbest[base + lane], acc);
    }
    __syncthreads();
    if (t < NG) atomicMax(&g_best_gt[b * NG + t], sbest[t]);
#pragma unroll
    for (int j = 0; j < 4; j++)
        g_matched[(size_t)b * NA + a0 + j * 256] = (bv[j] < RT) ? -1 : bg[j];
}

// ---------------- K2: scatter override: matched[best_anchor[g]] = g (last g wins) ------
__global__ void k_override() {
    int b = threadIdx.x;
    if (b < NB) {
#pragma unroll 8
        for (int g = 0; g < NG; g++) {
            unsigned long long v = g_best_gt[b * NG + g];
            unsigned a = 0xFFFFFFFFu - (unsigned)(v & 0xFFFFFFFFull);
            g_matched[(size_t)b * NA + a] = g;
        }
    }
}

// ---------------- K3: fused cls loss + bbox GIoU, warp-quad layout (no smem) ----------
// Each warp handles 4 anchors: lanes sweep classes coalesced (32+32+27), 4 parallel
// exp-sums, one interleaved 4-value butterfly, xt via single shfl per anchor.
// grid NB*NA/32 blocks of 256 threads (8 warps * 4 anchors = 32 anchors/block).
__global__ void __launch_bounds__(256) k_cls(const float*  __restrict__ logits,
                                             const int*    __restrict__ labels,
                                             const float4* __restrict__ reg,
                                             const float4* __restrict__ anchors,
                                             const float4* __restrict__ gt) {
    const int t = threadIdx.x;
    const int w = t >> 5, l = t & 31;
    const long long a0 = (long long)blockIdx.x * 32 + w * 4;  // anchors a0..a0+3
    const int b = (int)(a0 >> 15);                            // NA = 2^15

    // lanes 0-3 own anchors a0+0..a0+3
    int   m_own  = -1;
    int   tt_own = NC - 1;
    if (l < 4) {
        m_own = g_matched[a0 + l];
        if (m_own >= 0) tt_own = labels[b * NG + m_own];
    }

    // coalesced class sweep: 12 independent LDGs
    float x0[4], x1[4], x2[4];
#pragma unroll
    for (int k = 0; k < 4; k++) {
        const float* p = logits + (a0 + k) * NC;
        x0[k] = p[l];
        x1[k] = p[l + 32];
        x2[k] = (l < NC - 64) ? p[l + 64] : -1e30f;
    }

    float s[4];
#pragma unroll
    for (int k = 0; k < 4; k++)
        s[k] = __expf(x0[k]) + __expf(x1[k]) + __expf(x2[k]);

    // interleaved butterfly: 4 independent reduction chains
#pragma unroll
    for (int off = 16; off; off >>= 1) {
#pragma unroll
        for (int k = 0; k < 4; k++)
            s[k] += __shfl_xor_sync(0xFFFFFFFFu, s[k], off);
    }

    // per-anchor target logit + loss
    float closs[4];
#pragma unroll
    for (int k = 0; k < 4; k++) {
        int tt = __shfl_sync(0xFFFFFFFFu, tt_own, k);
        int slot = tt >> 5, src = tt & 31;
        float cand = (slot == 0) ? x0[k] : ((slot == 1) ? x1[k] : x2[k]);
        float xt = __shfl_sync(0xFFFFFFFFu, cand, src);
        closs[k] = fmaxf(__logf(s[k]) - xt, 0.0f);
    }

    // lanes 0-3: write negkey, bbox GIoU if fg, accumulate
    float myc = 0.0f, mybb = 0.0f;
    int myfg = 0;
    if (l < 4) {
        const bool fg = (m_own >= 0);
        g_negkey[a0 + l] = fg ? 0u : __float_as_uint(closs[l]);
        if (fg) {
            myfg = 1;
            myc = closs[l];
            float4 a  = anchors[a0 + l];
            float4 r  = reg[a0 + l];
            float4 gb = gt[b * NG + m_own];
            float ww = a.z - a.x, hh = a.w - a.y;
            float cx = a.x + 0.5f * ww, cy = a.y + 0.5f * hh;
            float dw = fminf(r.z, CLIPV), dh = fminf(r.w, CLIPV);
            float pcx = r.x * ww + cx, pcy = r.y * hh + cy;
            float pw = __expf(dw) * ww, ph = __expf(dh) * hh;
            float px0 = pcx - 0.5f * pw, py0 = pcy - 0.5f * ph;
            float px1 = pcx + 0.5f * pw, py1 = pcy + 0.5f * ph;
            float iw = fmaxf(fminf(px1, gb.z) - fmaxf(px0, gb.x), 0.0f);
            float ih = fmaxf(fminf(py1, gb.w) - fmaxf(py0, gb.y), 0.0f);
            float inter = iw * ih;
            float ap = (px1 - px0) * (py1 - py0);
            float ag = (gb.z - gb.x) * (gb.w - gb.y);
            float un = ap + ag - inter + 1e-16f;
            float iou = inter / un;
            float cw = fmaxf(px1, gb.z) - fminf(px0, gb.x);
            float ch = fmaxf(py1, gb.w) - fminf(py0, gb.y);
            float ac = cw * ch;
            float giou = iou - (ac - un) / fmaxf(ac, 1e-16f);
            mybb = 1.0f - fminf(fmaxf(giou, -1.0f), 1.0f);
        }
    }

    // reduce among lanes 0-3 (xor 1,2 closes the quad; other lanes contribute 0)
#pragma unroll
    for (int off = 1; off <= 2; off <<= 1) {
        myc  += __shfl_xor_sync(0xFFFFFFFFu, myc, off);
        mybb += __shfl_xor_sync(0xFFFFFFFFu, mybb, off);
        myfg += __shfl_xor_sync(0xFFFFFFFFu, myfg, off);
    }
    if (l == 0 && myfg > 0) {
        atomicAdd(&g_fgcls_sum, (double)myc);
        atomicAdd(&g_bbox_sum, (double)mybb);
        atomicAdd(&g_fgcnt[b], myfg);
    }
}

// ---------------- K4: per-batch radix-select + top-K sum (1024 threads) ----------------
__global__ void __launch_bounds__(1024) k_select() {
    const int b = blockIdx.x;
    const int t = threadIdx.x;
    int K = 3 * g_fgcnt[b];
    if (K <= 0) return;
    if (K > NA) K = NA;
    const unsigned* keys = g_negkey + (size_t)b * NA;

    __shared__ unsigned hist[256];
    __shared__ unsigned s_prefix;
    __shared__ int s_k;

    unsigned prefix = 0;
    int k = K;
    for (int byte = 3; byte >= 0; --byte) {
        const int sh = byte * 8;
        const unsigned mask = (byte == 3) ? 0u : (0xFFFFFFFFu << (sh + 8));
        if (t < 256) hist[t] = 0;
        __syncthreads();
#pragma unroll 4
        for (int i = t; i < NA; i += 1024) {
            unsigned key = keys[i];
            if ((key & mask) == prefix) atomicAdd(&hist[(key >> sh) & 255], 1u);
        }
        __syncthreads();
        if (t == 0) {
            int cum = 0;
            s_prefix = prefix; s_k = 0;
            for (int v = 255; v >= 0; --v) {
                int c = (int)hist[v];
                if (cum + c >= k) {
                    s_prefix = prefix | ((unsigned)v << sh);
                    s_k = k - cum;
                    break;
                }
                cum += c;
            }
        }
        __syncthreads();
        prefix = s_prefix;
        k = s_k;
        __syncthreads();
    }

    const float T = __uint_as_float(prefix);
    double local = 0.0;
#pragma unroll 4
    for (int i = t; i < NA; i += 1024) {
        unsigned key = keys[i];
        if (key > prefix) local += (double)__uint_as_float(key);
    }
    __shared__ double ssum[1024];
    ssum[t] = local;
    __syncthreads();
    for (int off = 512; off; off >>= 1) {
        if (t < off) ssum[t] += ssum[t + off];
        __syncthreads();
    }
    if (t == 0) atomicAdd(&g_neg_sum, ssum[0] + (double)k * (double)T);
}

// ---------------- K5: finalize ----------------
__global__ void k_final(float* __restrict__ out) {
    int tot = 0;
    for (int b = 0; b < NB; b++) tot += g_fgcnt[b];
    double N = (double)(tot > 1 ? tot : 1);
    out[0] = (float)(2.0 * g_bbox_sum / N);
    out[1] = (float)((g_fgcls_sum + g_neg_sum) / N);
}

// ---------------- launch ----------------
extern "C" void kernel_launch(void* const* d_in, const int* in_sizes, int n_in,
                              void* d_out, int out_size) {
    const float*  cls_logits = (const float*)d_in[0];
    const float4* bbox_reg   = (const float4*)d_in[1];
    const float4* anchors    = (const float4*)d_in[2];
    const float4* gt_boxes   = (const float4*)d_in[3];
    const int*    gt_labels  = (const int*)d_in[4];
    float* out = (float*)d_out;

    k_init<<<1, 256>>>();
    k_match<<<dim3(NA / 1024, NB), 256>>>(anchors, gt_boxes);
    k_override<<<1, 32>>>();
    k_cls<<<(NB * NA) / 32, 256>>>(cls_logits, gt_labels, bbox_reg, anchors, gt_boxes);
    k_select<<<NB, 1024>>>();
    k_final<<<1, 1>>>(out);
}

// round 8
// speedup vs baseline: 1.5160x; 1.5160x over previous
#include <cuda_runtime.h>
#include <math.h>

#define NB 32
#define NA 32768
#define NG 64
#define NC 91
#define RT 0.3103448275862069f   /* 0.45/1.45 : iou>=0.45  <=>  r=inter/S >= RT */
#define CLIPV 4.135166556742356f /* log(1000/16) */

#define CT 128                    /* anchors per k_cls tile */
#define TPT 16                    /* tiles per block */
#define TILE_F (CT * NC)          /* floats per tile = 11648 */
#define TILE_V4 (TILE_F / 4)      /* 2912 float4 */
#define CLS_SMEM (2 * TILE_F * 4) /* 93184 B dynamic */

#define CP_ASYNC16(su, gp) \
    asm volatile("cp.async.cg.shared.global [%0], [%1], 16;\n" :: "r"(su), "l"(gp))
#define CP_COMMIT() asm volatile("cp.async.commit_group;\n" ::: "memory")
#define CP_WAIT1()  asm volatile("cp.async.wait_group 1;\n" ::: "memory")
#define CP_WAIT0()  asm volatile("cp.async.wait_group 0;\n" ::: "memory")

// ---------------- scratch (static device globals; no runtime allocation) ----------------
__device__ int                 g_matched[NB * NA];
__device__ unsigned long long  g_best_gt[NB * NG];
__device__ unsigned            g_negkey[NB * NA];
__device__ int                 g_fgcnt[NB];
__device__ double              g_bbox_sum;
__device__ double              g_fgcls_sum;
__device__ double              g_neg_sum;

// ---------------- K0: zero accumulators (runs every replay) ----------------
__global__ void k_init() {
    int t = threadIdx.x;
    for (int i = t; i < NB * NG; i += blockDim.x) g_best_gt[i] = 0ull;
    if (t < NB) g_fgcnt[t] = 0;
    if (t == 0) { g_bbox_sum = 0.0; g_fgcls_sum = 0.0; g_neg_sum = 0.0; }
}

// ---------------- K1: IoU matching, 4 anchors/thread, both gt-chunks interleaved -------
// grid (NA/1024, NB), block 256. r = inter/(area_g+area_a): monotone in IoU.
__global__ void __launch_bounds__(256) k_match(const float4* __restrict__ anchors,
                                               const float4* __restrict__ gt) {
    __shared__ float4 sgt[NG];
    __shared__ float  sga[NG];
    __shared__ unsigned long long sbest[NG];
    const int b = blockIdx.y;
    const int t = threadIdx.x;
    const int lane = t & 31;
    if (t < NG) {
        float4 g = gt[b * NG + t];
        sgt[t] = g;
        sga[t] = (g.z - g.x) * (g.w - g.y);
        sbest[t] = 0ull;
    }
    __syncthreads();

    const int a0 = blockIdx.x * 1024 + t;  // anchors a0 + j*256, j=0..3
    float ax0[4], ay0[4], ax1[4], ay1[4], aar[4], bv[4];
    int bg[4];
#pragma unroll
    for (int j = 0; j < 4; j++) {
        float4 a = anchors[(size_t)b * NA + a0 + j * 256];
        ax0[j] = a.x; ay0[j] = a.y; ax1[j] = a.z; ay1[j] = a.w;
        aar[j] = (a.z - a.x) * (a.w - a.y);
        bv[j] = 0.0f; bg[j] = 0;
    }

    unsigned long long accL = 0ull, accH = 0ull;  // per-gt best for g=lane, g=32+lane
    for (int i = 0; i < 32; i++) {
        const int gl = (lane + i) & 31;
        const int gh = 32 + gl;
        const float4 gbL = sgt[gl]; const float gaL = sga[gl];
        const float4 gbH = sgt[gh]; const float gaH = sga[gh];
        float crL = 0.0f, crH = 0.0f; int caL = a0, caH = a0;
#pragma unroll
        for (int j = 0; j < 4; j++) {
            float wL = fminf(gbL.z, ax1[j]) - fmaxf(gbL.x, ax0[j]);
            float hL = fminf(gbL.w, ay1[j]) - fmaxf(gbL.y, ay0[j]);
            float wH = fminf(gbH.z, ax1[j]) - fmaxf(gbH.x, ax0[j]);
            float hH = fminf(gbH.w, ay1[j]) - fmaxf(gbH.y, ay0[j]);
            wL = fmaxf(wL, 0.0f); hL = fmaxf(hL, 0.0f);
            wH = fmaxf(wH, 0.0f); hH = fmaxf(hH, 0.0f);
            float rL = __fdividef(wL * hL, gaL + aar[j]);
            float rH = __fdividef(wH * hH, gaH + aar[j]);
            if (rL > bv[j]) { bv[j] = rL; bg[j] = gl; }       // lower g first within iter
            if (rH > bv[j]) { bv[j] = rH; bg[j] = gh; }
            if (rL > crL)   { crL = rL; caL = a0 + j * 256; } // lowest anchor wins ties
            if (rH > crH)   { crH = rH; caH = a0 + j * 256; }
        }
        unsigned long long candL =
            ((unsigned long long)__float_as_uint(crL) << 32) |
            (unsigned long long)(0xFFFFFFFFu - (unsigned)caL);
        unsigned long long candH =
            ((unsigned long long)__float_as_uint(crH) << 32) |
            (unsigned long long)(0xFFFFFFFFu - (unsigned)caH);
        unsigned long long rL = __shfl_sync(0xFFFFFFFFu, candL, (lane - i) & 31);
        unsigned long long rH = __shfl_sync(0xFFFFFFFFu, candH, (lane - i) & 31);
        accL = (rL > accL) ? rL : accL;
        accH = (rH > accH) ? rH : accH;
    }
    atomicMax(&sbest[lane], accL);
    atomicMax(&sbest[32 + lane], accH);
    __syncthreads();
    if (t < NG) atomicMax(&g_best_gt[b * NG + t], sbest[t]);
#pragma unroll
    for (int j = 0; j < 4; j++)
        g_matched[(size_t)b * NA + a0 + j * 256] = (bv[j] < RT) ? -1 : bg[j];
}

// ---------------- K2: scatter override: matched[best_anchor[g]] = g (last g wins) ------
__global__ void k_override() {
    int b = threadIdx.x;
    if (b < NB) {
#pragma unroll 8
        for (int g = 0; g < NG; g++) {
            unsigned long long v = g_best_gt[b * NG + g];
            unsigned a = 0xFFFFFFFFu - (unsigned)(v & 0xFFFFFFFFull);
            g_matched[(size_t)b * NA + a] = g;
        }
    }
}

// ---------------- K3: fused cls + bbox, cp.async double-buffered pipeline --------------
// block = CT threads; each block processes TPT tiles of CT anchors; prefetch tile k+1
// while computing tile k. smem row stride NC=91: gcd(91,32)=1 -> conflict-free.
__global__ void __launch_bounds__(CT) k_cls(const float*  __restrict__ logits,
                                            const int*    __restrict__ labels,
                                            const float4* __restrict__ reg,
                                            const float4* __restrict__ anchors,
                                            const float4* __restrict__ gt) {
    extern __shared__ float s[];  // 2 * TILE_F floats
    __shared__ float wsum[CT / 32], wbb[CT / 32];
    __shared__ int   wcnt[CT / 32];
    const int t = threadIdx.x;
    const long long a_base = (long long)blockIdx.x * (TPT * CT);
    const int b = (int)(a_base >> 15);  // NA = 2^15; TPT*CT divides NA
    const int* lab = labels + b * NG;

    // prefetch tile 0
    {
        const float4* src = (const float4*)(logits + a_base * NC);
        unsigned su = (unsigned)__cvta_generic_to_shared(s);
#pragma unroll 4
        for (int i = t; i < TILE_V4; i += CT) CP_ASYNC16(su + i * 16, src + i);
        CP_COMMIT();
    }

    float accC = 0.0f, accB = 0.0f;
    int accF = 0;

    for (int k = 0; k < TPT; k++) {
        if (k + 1 < TPT) {
            const float4* src = (const float4*)(logits + (a_base + (long long)(k + 1) * CT) * NC);
            unsigned su = (unsigned)__cvta_generic_to_shared(s + ((k + 1) & 1) * TILE_F);
#pragma unroll 4
            for (int i = t; i < TILE_V4; i += CT) CP_ASYNC16(su + i * 16, src + i);
            CP_COMMIT();
            CP_WAIT1();
        } else {
            CP_WAIT0();
        }
        __syncthreads();

        const long long a = a_base + (long long)k * CT + t;
        const int matched = g_matched[a];
        const bool fg = (matched >= 0);
        const int tt = fg ? lab[matched] : (NC - 1);

        const float* row = s + (k & 1) * TILE_F + t * NC;
        float s0 = 0.f, s1 = 0.f, s2 = 0.f, s3 = 0.f;
#pragma unroll
        for (int i = 0; i < 88; i += 4) {
            s0 += __expf(row[i]);     s1 += __expf(row[i + 1]);
            s2 += __expf(row[i + 2]); s3 += __expf(row[i + 3]);
        }
        s0 += __expf(row[88]); s1 += __expf(row[89]); s2 += __expf(row[90]);
        const float lse = __logf((s0 + s1) + (s2 + s3));
        const float closs = fmaxf(lse - row[tt], 0.0f);
        g_negkey[a] = fg ? 0u : __float_as_uint(closs);

        if (fg) {
            accF += 1;
            accC += closs;
            float4 an = anchors[a];
            float4 r  = reg[a];
            float4 gb = gt[b * NG + matched];
            float ww = an.z - an.x, hh = an.w - an.y;
            float cx = an.x + 0.5f * ww, cy = an.y + 0.5f * hh;
            float dw = fminf(r.z, CLIPV), dh = fminf(r.w, CLIPV);
            float pcx = r.x * ww + cx, pcy = r.y * hh + cy;
            float pw = __expf(dw) * ww, ph = __expf(dh) * hh;
            float px0 = pcx - 0.5f * pw, py0 = pcy - 0.5f * ph;
            float px1 = pcx + 0.5f * pw, py1 = pcy + 0.5f * ph;
            float iw = fmaxf(fminf(px1, gb.z) - fmaxf(px0, gb.x), 0.0f);
            float ih = fmaxf(fminf(py1, gb.w) - fmaxf(py0, gb.y), 0.0f);
            float inter = iw * ih;
            float ap = (px1 - px0) * (py1 - py0);
            float ag = (gb.z - gb.x) * (gb.w - gb.y);
            float un = ap + ag - inter + 1e-16f;
            float iou = inter / un;
            float cw = fmaxf(px1, gb.z) - fminf(px0, gb.x);
            float ch = fmaxf(py1, gb.w) - fminf(py0, gb.y);
            float ac = cw * ch;
            float giou = iou - (ac - un) / fmaxf(ac, 1e-16f);
            accB += 1.0f - fminf(fmaxf(giou, -1.0f), 1.0f);
        }
        __syncthreads();  // buffer reuse guard
    }

    // block-level reduction -> <=3 atomics per block
    unsigned _ = __ballot_sync(0xFFFFFFFFu, 1);
#pragma unroll
    for (int off = 16; off; off >>= 1) {
        accC += __shfl_xor_sync(0xFFFFFFFFu, accC, off);
        accB += __shfl_xor_sync(0xFFFFFFFFu, accB, off);
        accF += __shfl_xor_sync(0xFFFFFFFFu, accF, off);
    }
    if ((t & 31) == 0) { wsum[t >> 5] = accC; wbb[t >> 5] = accB; wcnt[t >> 5] = accF; }
    __syncthreads();
    if (t == 0) {
        float fs = 0.f, fb = 0.f; int fc = 0;
#pragma unroll
        for (int w = 0; w < CT / 32; w++) { fs += wsum[w]; fb += wbb[w]; fc += wcnt[w]; }
        if (fc > 0) {
            atomicAdd(&g_fgcls_sum, (double)fs);
            atomicAdd(&g_bbox_sum, (double)fb);
            atomicAdd(&g_fgcnt[b], fc);
        }
    }
}

// ---------------- K4: per-batch radix-select + top-K sum (1024 threads) ----------------
__global__ void __launch_bounds__(1024) k_select() {
    const int b = blockIdx.x;
    const int t = threadIdx.x;
    int K = 3 * g_fgcnt[b];
    if (K <= 0) return;
    if (K > NA) K = NA;
    const unsigned* keys = g_negkey + (size_t)b * NA;

    __shared__ unsigned hist[256];
    __shared__ unsigned s_prefix;
    __shared__ int s_k;

    unsigned prefix = 0;
    int k = K;
    for (int byte = 3; byte >= 0; --byte) {
        const int sh = byte * 8;
        const unsigned mask = (byte == 3) ? 0u : (0xFFFFFFFFu << (sh + 8));
        if (t < 256) hist[t] = 0;
        __syncthreads();
#pragma unroll 4
        for (int i = t; i < NA; i += 1024) {
            unsigned key = keys[i];
            if ((key & mask) == prefix) atomicAdd(&hist[(key >> sh) & 255], 1u);
        }
        __syncthreads();
        if (t == 0) {
            int cum = 0;
            s_prefix = prefix; s_k = 0;
            for (int v = 255; v >= 0; --v) {
                int c = (int)hist[v];
                if (cum + c >= k) {
                    s_prefix = prefix | ((unsigned)v << sh);
                    s_k = k - cum;
                    break;
                }
                cum += c;
            }
        }
        __syncthreads();
        prefix = s_prefix;
        k = s_k;
        __syncthreads();
    }

    const float T = __uint_as_float(prefix);
    double local = 0.0;
#pragma unroll 4
    for (int i = t; i < NA; i += 1024) {
        unsigned key = keys[i];
        if (key > prefix) local += (double)__uint_as_float(key);
    }
    __shared__ double ssum[1024];
    ssum[t] = local;
    __syncthreads();
    for (int off = 512; off; off >>= 1) {
        if (t < off) ssum[t] += ssum[t + off];
        __syncthreads();
    }
    if (t == 0) atomicAdd(&g_neg_sum, ssum[0] + (double)k * (double)T);
}

// ---------------- K5: finalize ----------------
__global__ void k_final(float* __restrict__ out) {
    int tot = 0;
    for (int b = 0; b < NB; b++) tot += g_fgcnt[b];
    double N = (double)(tot > 1 ? tot : 1);
    out[0] = (float)(2.0 * g_bbox_sum / N);
    out[1] = (float)((g_fgcls_sum + g_neg_sum) / N);
}

// ---------------- launch ----------------
extern "C" void kernel_launch(void* const* d_in, const int* in_sizes, int n_in,
                              void* d_out, int out_size) {
    const float*  cls_logits = (const float*)d_in[0];
    const float4* bbox_reg   = (const float4*)d_in[1];
    const float4* anchors    = (const float4*)d_in[2];
    const float4* gt_boxes   = (const float4*)d_in[3];
    const int*    gt_labels  = (const int*)d_in[4];
    float* out = (float*)d_out;

    cudaFuncSetAttribute(k_cls, cudaFuncAttributeMaxDynamicSharedMemorySize, CLS_SMEM);

    k_init<<<1, 256>>>();
    k_match<<<dim3(NA / 1024, NB), 256>>>(anchors, gt_boxes);
    k_override<<<1, 32>>>();
    k_cls<<<(NB * NA) / (TPT * CT), CT, CLS_SMEM>>>(cls_logits, gt_labels, bbox_reg,
                                                    anchors, gt_boxes);
    k_select<<<NB, 1024>>>();
    k_final<<<1, 1>>>(out);
}

// round 9
// speedup vs baseline: 1.6512x; 1.0892x over previous
#include <cuda_runtime.h>
#include <math.h>

#define NB 32
#define NA 32768
#define NG 64
#define NC 91
#define RT 0.3103448275862069f   /* 0.45/1.45 : iou>=0.45  <=>  r=inter/S >= RT */
#define CLIPV 4.135166556742356f /* log(1000/16) */

#define CT 128                    /* anchors per k_cls tile */
#define TPT 8                     /* tiles per block */
#define TILE_F (CT * NC)          /* floats per tile = 11648 */
#define TILE_V4 (TILE_F / 4)      /* 2912 float4 */
#define CLS_SMEM (2 * TILE_F * 4) /* 93184 B dynamic */

#define CP_ASYNC16(su, gp) \
    asm volatile("cp.async.cg.shared.global [%0], [%1], 16;\n" :: "r"(su), "l"(gp))
#define CP_COMMIT() asm volatile("cp.async.commit_group;\n" ::: "memory")
#define CP_WAIT1()  asm volatile("cp.async.wait_group 1;\n" ::: "memory")
#define CP_WAIT0()  asm volatile("cp.async.wait_group 0;\n" ::: "memory")

// ---------------- scratch (static device globals; no runtime allocation) ----------------
__device__ int                 g_matched[NB * NA];
__device__ unsigned long long  g_best_gt[NB * NG];
__device__ unsigned            g_negkey[NB * NA];
__device__ int                 g_fgcnt[NB];
__device__ double              g_bbox_sum;
__device__ double              g_fgcls_sum;
__device__ double              g_neg_sum;

// ---------------- K0: zero accumulators (runs every replay) ----------------
__global__ void k_init() {
    int t = threadIdx.x;
    for (int i = t; i < NB * NG; i += blockDim.x) g_best_gt[i] = 0ull;
    if (t < NB) g_fgcnt[t] = 0;
    if (t == 0) { g_bbox_sum = 0.0; g_fgcls_sum = 0.0; g_neg_sum = 0.0; }
}

// ---------------- K1: IoU matching, 4 anchors/thread, both gt-chunks interleaved -------
__global__ void __launch_bounds__(256) k_match(const float4* __restrict__ anchors,
                                               const float4* __restrict__ gt) {
    __shared__ float4 sgt[NG];
    __shared__ float  sga[NG];
    __shared__ unsigned long long sbest[NG];
    const int b = blockIdx.y;
    const int t = threadIdx.x;
    const int lane = t & 31;
    if (t < NG) {
        float4 g = gt[b * NG + t];
        sgt[t] = g;
        sga[t] = (g.z - g.x) * (g.w - g.y);
        sbest[t] = 0ull;
    }
    __syncthreads();

    const int a0 = blockIdx.x * 1024 + t;  // anchors a0 + j*256, j=0..3
    float ax0[4], ay0[4], ax1[4], ay1[4], aar[4], bv[4];
    int bg[4];
#pragma unroll
    for (int j = 0; j < 4; j++) {
        float4 a = anchors[(size_t)b * NA + a0 + j * 256];
        ax0[j] = a.x; ay0[j] = a.y; ax1[j] = a.z; ay1[j] = a.w;
        aar[j] = (a.z - a.x) * (a.w - a.y);
        bv[j] = 0.0f; bg[j] = 0;
    }

    unsigned long long accL = 0ull, accH = 0ull;  // per-gt best for g=lane, g=32+lane
    for (int i = 0; i < 32; i++) {
        const int gl = (lane + i) & 31;
        const int gh = 32 + gl;
        const float4 gbL = sgt[gl]; const float gaL = sga[gl];
        const float4 gbH = sgt[gh]; const float gaH = sga[gh];
        float crL = 0.0f, crH = 0.0f; int caL = a0, caH = a0;
#pragma unroll
        for (int j = 0; j < 4; j++) {
            float wL = fminf(gbL.z, ax1[j]) - fmaxf(gbL.x, ax0[j]);
            float hL = fminf(gbL.w, ay1[j]) - fmaxf(gbL.y, ay0[j]);
            float wH = fminf(gbH.z, ax1[j]) - fmaxf(gbH.x, ax0[j]);
            float hH = fminf(gbH.w, ay1[j]) - fmaxf(gbH.y, ay0[j]);
            wL = fmaxf(wL, 0.0f); hL = fmaxf(hL, 0.0f);
            wH = fmaxf(wH, 0.0f); hH = fmaxf(hH, 0.0f);
            float rL = __fdividef(wL * hL, gaL + aar[j]);
            float rH = __fdividef(wH * hH, gaH + aar[j]);
            if (rL > bv[j]) { bv[j] = rL; bg[j] = gl; }
            if (rH > bv[j]) { bv[j] = rH; bg[j] = gh; }
            if (rL > crL)   { crL = rL; caL = a0 + j * 256; }
            if (rH > crH)   { crH = rH; caH = a0 + j * 256; }
        }
        unsigned long long candL =
            ((unsigned long long)__float_as_uint(crL) << 32) |
            (unsigned long long)(0xFFFFFFFFu - (unsigned)caL);
        unsigned long long candH =
            ((unsigned long long)__float_as_uint(crH) << 32) |
            (unsigned long long)(0xFFFFFFFFu - (unsigned)caH);
        unsigned long long rL = __shfl_sync(0xFFFFFFFFu, candL, (lane - i) & 31);
        unsigned long long rH = __shfl_sync(0xFFFFFFFFu, candH, (lane - i) & 31);
        accL = (rL > accL) ? rL : accL;
        accH = (rH > accH) ? rH : accH;
    }
    atomicMax(&sbest[lane], accL);
    atomicMax(&sbest[32 + lane], accH);
    __syncthreads();
    if (t < NG) atomicMax(&g_best_gt[b * NG + t], sbest[t]);
#pragma unroll
    for (int j = 0; j < 4; j++)
        g_matched[(size_t)b * NA + a0 + j * 256] = (bv[j] < RT) ? -1 : bg[j];
}

// ---------------- K2: scatter override: matched[best_anchor[g]] = g (last g wins) ------
__global__ void k_override() {
    int b = threadIdx.x;
    if (b < NB) {
#pragma unroll 8
        for (int g = 0; g < NG; g++) {
            unsigned long long v = g_best_gt[b * NG + g];
            unsigned a = 0xFFFFFFFFu - (unsigned)(v & 0xFFFFFFFFull);
            g_matched[(size_t)b * NA + a] = g;
        }
    }
}

// ---------------- K3: fused cls + bbox, 2 threads/anchor, cp.async double buffer -------
// block 256 threads, tile = 128 anchors. Thread t<128 sums classes [0,46) of anchor t,
// thread t+128 sums classes [46,91); halves merged through smem. 2 blocks/SM ->
// 16 warps/SM: MUFU issue packs to its floor and the cp.async stream keeps DRAM busy.
__global__ void __launch_bounds__(256) k_cls(const float*  __restrict__ logits,
                                             const int*    __restrict__ labels,
                                             const float4* __restrict__ reg,
                                             const float4* __restrict__ anchors,
                                             const float4* __restrict__ gt) {
    extern __shared__ float s[];  // 2 * TILE_F floats
    __shared__ float part_s[CT], part_x[CT];
    __shared__ float wsum[8], wbb[8];
    __shared__ int   wcnt[8];
    const int t = threadIdx.x;
    const int half = t >> 7;      // 0: classes 0-45, 1: classes 46-90
    const int ta = t & 127;       // anchor within tile
    const long long a_base = (long long)blockIdx.x * (TPT * CT);
    const int b = (int)(a_base >> 15);  // NA = 2^15
    const int* lab = labels + b * NG;

    // prologue: prefetch tile 0
    {
        const float4* src = (const float4*)(logits + a_base * NC);
        unsigned su = (unsigned)__cvta_generic_to_shared(s);
#pragma unroll 4
        for (int i = t; i < TILE_V4; i += 256) CP_ASYNC16(su + i * 16, src + i);
        CP_COMMIT();
    }

    float accC = 0.0f, accB = 0.0f;
    int accF = 0;

    for (int k = 0; k < TPT; k++) {
        if (k + 1 < TPT) {
            const float4* src = (const float4*)(logits + (a_base + (long long)(k + 1) * CT) * NC);
            unsigned su = (unsigned)__cvta_generic_to_shared(s + ((k + 1) & 1) * TILE_F);
#pragma unroll 4
            for (int i = t; i < TILE_V4; i += 256) CP_ASYNC16(su + i * 16, src + i);
            CP_COMMIT();
            CP_WAIT1();
        } else {
            CP_WAIT0();
        }
        __syncthreads();  // buffer ready + prior tile's smem reads complete

        const long long a = a_base + (long long)k * CT + ta;
        const int matched = g_matched[a];
        const bool fg = (matched >= 0);
        const int tt = fg ? lab[matched] : (NC - 1);

        // stride-91 rows, half offset 46: gcd(91,32)=1 -> conflict-free
        const float* row = s + (k & 1) * TILE_F + ta * NC + half * 46;
        float s0 = 0.f, s1 = 0.f, s2 = 0.f, s3 = 0.f;
#pragma unroll
        for (int i = 0; i < 44; i += 4) {
            s0 += __expf(row[i]);     s1 += __expf(row[i + 1]);
            s2 += __expf(row[i + 2]); s3 += __expf(row[i + 3]);
        }
        s0 += __expf(row[44]);
        if (half == 0) s1 += __expf(row[45]);
        const float ps = (s0 + s1) + (s2 + s3);

        const int ttl = tt - half * 46;
        const int lim = half ? 45 : 46;
        const float xcand = (ttl >= 0 && ttl < lim) ? row[ttl] : 0.0f;
        if (half) { part_s[ta] = ps; part_x[ta] = xcand; }
        __syncthreads();  // partials ready; all buffer reads done

        if (!half) {
            const float S = ps + part_s[ta];
            const float xt = (tt < 46) ? xcand : part_x[ta];
            const float closs = fmaxf(__logf(S) - xt, 0.0f);
            g_negkey[a] = fg ? 0u : __float_as_uint(closs);
            if (fg) {
                accF += 1;
                accC += closs;
                float4 an = anchors[a];
                float4 r  = reg[a];
                float4 gb = gt[b * NG + matched];
                float ww = an.z - an.x, hh = an.w - an.y;
                float cx = an.x + 0.5f * ww, cy = an.y + 0.5f * hh;
                float dw = fminf(r.z, CLIPV), dh = fminf(r.w, CLIPV);
                float pcx = r.x * ww + cx, pcy = r.y * hh + cy;
                float pw = __expf(dw) * ww, ph = __expf(dh) * hh;
                float px0 = pcx - 0.5f * pw, py0 = pcy - 0.5f * ph;
                float px1 = pcx + 0.5f * pw, py1 = pcy + 0.5f * ph;
                float iw = fmaxf(fminf(px1, gb.z) - fmaxf(px0, gb.x), 0.0f);
                float ih = fmaxf(fminf(py1, gb.w) - fmaxf(py0, gb.y), 0.0f);
                float inter = iw * ih;
                float ap = (px1 - px0) * (py1 - py0);
                float ag = (gb.z - gb.x) * (gb.w - gb.y);
                float un = ap + ag - inter + 1e-16f;
                float iou = inter / un;
                float cw = fmaxf(px1, gb.z) - fminf(px0, gb.x);
                float ch = fmaxf(py1, gb.w) - fminf(py0, gb.y);
                float ac = cw * ch;
                float giou = iou - (ac - un) / fmaxf(ac, 1e-16f);
                accB += 1.0f - fminf(fmaxf(giou, -1.0f), 1.0f);
            }
        }
    }

    // block-level reduction (high threads contribute zeros) -> <=3 atomics per block
#pragma unroll
    for (int off = 16; off; off >>= 1) {
        accC += __shfl_xor_sync(0xFFFFFFFFu, accC, off);
        accB += __shfl_xor_sync(0xFFFFFFFFu, accB, off);
        accF += __shfl_xor_sync(0xFFFFFFFFu, accF, off);
    }
    if ((t & 31) == 0) { wsum[t >> 5] = accC; wbb[t >> 5] = accB; wcnt[t >> 5] = accF; }
    __syncthreads();
    if (t == 0) {
        float fs = 0.f, fb = 0.f; int fc = 0;
#pragma unroll
        for (int w = 0; w < 8; w++) { fs += wsum[w]; fb += wbb[w]; fc += wcnt[w]; }
        if (fc > 0) {
            atomicAdd(&g_fgcls_sum, (double)fs);
            atomicAdd(&g_bbox_sum, (double)fb);
            atomicAdd(&g_fgcnt[b], fc);
        }
    }
}

// ---------------- K4: per-batch radix-select + top-K sum (1024 threads) ----------------
__global__ void __launch_bounds__(1024) k_select() {
    const int b = blockIdx.x;
    const int t = threadIdx.x;
    int K = 3 * g_fgcnt[b];
    if (K <= 0) return;
    if (K > NA) K = NA;
    const unsigned* keys = g_negkey + (size_t)b * NA;

    __shared__ unsigned hist[256];
    __shared__ unsigned s_prefix;
    __shared__ int s_k;

    unsigned prefix = 0;
    int k = K;
    for (int byte = 3; byte >= 0; --byte) {
        const int sh = byte * 8;
        const unsigned mask = (byte == 3) ? 0u : (0xFFFFFFFFu << (sh + 8));
        if (t < 256) hist[t] = 0;
        __syncthreads();
#pragma unroll 4
        for (int i = t; i < NA; i += 1024) {
            unsigned key = keys[i];
            if ((key & mask) == prefix) atomicAdd(&hist[(key >> sh) & 255], 1u);
        }
        __syncthreads();
        if (t == 0) {
            int cum = 0;
            s_prefix = prefix; s_k = 0;
            for (int v = 255; v >= 0; --v) {
                int c = (int)hist[v];
                if (cum + c >= k) {
                    s_prefix = prefix | ((unsigned)v << sh);
                    s_k = k - cum;
                    break;
                }
                cum += c;
            }
        }
        __syncthreads();
        prefix = s_prefix;
        k = s_k;
        __syncthreads();
    }

    const float T = __uint_as_float(prefix);
    double local = 0.0;
#pragma unroll 4
    for (int i = t; i < NA; i += 1024) {
        unsigned key = keys[i];
        if (key > prefix) local += (double)__uint_as_float(key);
    }
    __shared__ double ssum[1024];
    ssum[t] = local;
    __syncthreads();
    for (int off = 512; off; off >>= 1) {
        if (t < off) ssum[t] += ssum[t + off];
        __syncthreads();
    }
    if (t == 0) atomicAdd(&g_neg_sum, ssum[0] + (double)k * (double)T);
}

// ---------------- K5: finalize ----------------
__global__ void k_final(float* __restrict__ out) {
    int tot = 0;
    for (int b = 0; b < NB; b++) tot += g_fgcnt[b];
    double N = (double)(tot > 1 ? tot : 1);
    out[0] = (float)(2.0 * g_bbox_sum / N);
    out[1] = (float)((g_fgcls_sum + g_neg_sum) / N);
}

// ---------------- launch ----------------
extern "C" void kernel_launch(void* const* d_in, const int* in_sizes, int n_in,
                              void* d_out, int out_size) {
    const float*  cls_logits = (const float*)d_in[0];
    const float4* bbox_reg   = (const float4*)d_in[1];
    const float4* anchors    = (const float4*)d_in[2];
    const float4* gt_boxes   = (const float4*)d_in[3];
    const int*    gt_labels  = (const int*)d_in[4];
    float* out = (float*)d_out;

    cudaFuncSetAttribute(k_cls, cudaFuncAttributeMaxDynamicSharedMemorySize, CLS_SMEM);

    k_init<<<1, 256>>>();
    k_match<<<dim3(NA / 1024, NB), 256>>>(anchors, gt_boxes);
    k_override<<<1, 32>>>();
    k_cls<<<(NB * NA) / (TPT * CT), 256, CLS_SMEM>>>(cls_logits, gt_labels, bbox_reg,
                                                     anchors, gt_boxes);
    k_select<<<NB, 1024>>>();
    k_final<<<1, 1>>>(out);
}